// round 4
// baseline (speedup 1.0000x reference)
#include <cuda_runtime.h>
#include <cuda_bf16.h>
#include <cstdint>
#include <cfloat>

#define NQ 32
#define DIM 128
#define KTOP 10
#define TM 128
#define TPB 128
#define NBLK 592
#define NLISTS (NBLK * 4)
#define POOLCAP (NLISTS * KTOP)      // full capacity: no overflow possible
#define MARGIN 3e-3f

// ---------------- device globals (no allocations allowed) ----------------
__device__ float    g_qnf[NQ * DIM];          // exact normalized queries fp32
__device__ uint32_t g_qbf2[NQ * 64];          // normalized queries bf16x2 [q][64]
__device__ unsigned g_thresh_enc[NQ];         // global per-query threshold (order-encoded)
__device__ int      g_poolcnt[NQ];
__device__ float    g_candS[NLISTS * NQ * KTOP];
__device__ int      g_candI[NLISTS * NQ * KTOP];
__device__ float    g_poolS[NQ * POOLCAP];
__device__ int      g_poolI[NQ * POOLCAP];

// ---------------- helpers ----------------
__device__ __forceinline__ unsigned encf(float f) {
    unsigned u = __float_as_uint(f);
    return u ^ ((u & 0x80000000u) ? 0xFFFFFFFFu : 0x80000000u);
}
__device__ __forceinline__ float decf(unsigned e) {
    unsigned u = (e & 0x80000000u) ? (e ^ 0x80000000u) : ~e;
    return __uint_as_float(u);
}
__device__ __forceinline__ uint32_t smem_u32(const void* p) {
    uint32_t a;
    asm("{ .reg .u64 t; cvta.to.shared.u64 t, %1; cvt.u32.u64 %0, t; }" : "=r"(a) : "l"(p));
    return a;
}
__device__ __forceinline__ uint32_t pack_bf16x2(float lo, float hi) {
    uint32_t r;
    asm("cvt.rn.bf16x2.f32 %0, %1, %2;" : "=r"(r) : "f"(hi), "f"(lo));  // first src -> high half
    return r;
}
__device__ __forceinline__ void ldm_x4(uint32_t& r0, uint32_t& r1, uint32_t& r2, uint32_t& r3,
                                       uint32_t addr) {
    asm volatile("ldmatrix.sync.aligned.m8n8.x4.shared.b16 {%0,%1,%2,%3}, [%4];"
                 : "=r"(r0), "=r"(r1), "=r"(r2), "=r"(r3) : "r"(addr));
}
__device__ __forceinline__ void ldm_x2(uint32_t& r0, uint32_t& r1, uint32_t addr) {
    asm volatile("ldmatrix.sync.aligned.m8n8.x2.shared.b16 {%0,%1}, [%2];"
                 : "=r"(r0), "=r"(r1) : "r"(addr));
}
__device__ __forceinline__ void mma_bf16(float* d, uint32_t a0, uint32_t a1, uint32_t a2,
                                         uint32_t a3, uint32_t b0, uint32_t b1) {
    asm volatile(
        "mma.sync.aligned.m16n8k16.row.col.f32.bf16.bf16.f32 "
        "{%0,%1,%2,%3}, {%4,%5,%6,%7}, {%8,%9}, {%0,%1,%2,%3};"
        : "+f"(d[0]), "+f"(d[1]), "+f"(d[2]), "+f"(d[3])
        : "r"(a0), "r"(a1), "r"(a2), "r"(a3), "r"(b0), "r"(b1));
}
__device__ __forceinline__ float warp_sum(float v) {
    #pragma unroll
    for (int o = 16; o; o >>= 1) v += __shfl_xor_sync(0xffffffffu, v, o);
    return v;
}

// ============================================================
// Kernel 1: prep — normalize queries; warm-start global thresholds from
// an exact fp32 scan of the first 128 corpus rows. 32 warps, warp = query.
// ============================================================
__global__ void prep_kernel(const float* __restrict__ q,
                            const float* __restrict__ corpus, int nrows) {
    const int qi = threadIdx.x >> 5, lane = threadIdx.x & 31;
    float4 v = ((const float4*)q)[qi * (DIM / 4) + lane];
    float ss = warp_sum(v.x * v.x + v.y * v.y + v.z * v.z + v.w * v.w);
    float inv = 1.0f / fmaxf(sqrtf(ss), 1e-12f);
    float4 s = make_float4(v.x * inv, v.y * inv, v.z * inv, v.w * inv);
    ((float4*)g_qnf)[qi * (DIM / 4) + lane] = s;
    g_qbf2[qi * 64 + lane * 2]     = pack_bf16x2(s.x, s.y);
    g_qbf2[qi * 64 + lane * 2 + 1] = pack_bf16x2(s.z, s.w);

    float top[KTOP];
    #pragma unroll
    for (int t = 0; t < KTOP; t++) top[t] = -FLT_MAX;

    int warm = nrows < 128 ? nrows : 128;
    for (int r = 0; r < warm; r++) {
        float4 c = ((const float4*)corpus)[r * (DIM / 4) + lane];
        float d  = c.x * s.x + c.y * s.y + c.z * s.z + c.w * s.w;
        float n2 = c.x * c.x + c.y * c.y + c.z * c.z + c.w * c.w;
        #pragma unroll
        for (int o = 16; o; o >>= 1) {
            d  += __shfl_xor_sync(0xffffffffu, d, o);
            n2 += __shfl_xor_sync(0xffffffffu, n2, o);
        }
        if (lane == 0) {
            float sc = d / fmaxf(sqrtf(n2), 1e-12f);
            float mn = top[0]; int mp = 0;
            #pragma unroll
            for (int t = 1; t < KTOP; t++)
                if (top[t] < mn) { mn = top[t]; mp = t; }
            if (sc > mn) top[mp] = sc;
        }
    }
    if (lane == 0) {
        float mn = top[0];
        #pragma unroll
        for (int t = 1; t < KTOP; t++) mn = fminf(mn, top[t]);
        g_thresh_enc[qi] = encf(mn - MARGIN);
        g_poolcnt[qi] = 0;
    }
}

// ============================================================
// Kernel 2: HMMA scoring + fused top-k. Warp-private 32-row tiles.
// ============================================================
__global__ void __launch_bounds__(TPB, 4)
score_mma(const float* __restrict__ corpus, int nrows, int ntiles) {
    __shared__ __align__(16) __nv_bfloat16 sA[4][32][136];   // 34816 B (row stride 272B)
    __shared__ float sInv[4][32];
    __shared__ float sTopS[4][NQ][KTOP];
    __shared__ int   sTopI[4][NQ][KTOP];
    __shared__ float sKmin[4][NQ];

    const int tid = threadIdx.x, w = tid >> 5, lane = tid & 31;

    for (int i = tid; i < 4 * NQ * KTOP; i += TPB) {
        ((float*)sTopS)[i] = -FLT_MAX;
        ((int*)sTopI)[i] = 0x7fffffff;
    }
    for (int i = tid; i < 4 * NQ; i += TPB) ((float*)sKmin)[i] = -FLT_MAX;

    // ---- stage normalized bf16 queries into sA region, ldmatrix B frags ----
    for (int idx = tid; idx < NQ * 64; idx += TPB) {
        int qr = idx >> 6, c = idx & 63;
        *(uint32_t*)((char*)sA + qr * 272 + c * 4) = g_qbf2[idx];
    }
    __syncthreads();

    uint32_t b[4][8][2];
    {
        uint32_t qbase = smem_u32(&sA[0][0][0]);
        int l = lane & 15;
        #pragma unroll
        for (int nt = 0; nt < 4; nt++)
            #pragma unroll
            for (int kk = 0; kk < 8; kk++) {
                uint32_t addr = qbase + (nt * 8 + (l & 7)) * 272 + kk * 32 + ((l >> 3) << 4);
                ldm_x2(b[nt][kk][0], b[nt][kk][1], addr);
            }
    }
    __syncthreads();

    const uint32_t abase = smem_u32(&sA[w][0][0]);
    const uint32_t a_addr0 = abase + (lane & 15) * 272 + ((lane >> 4) << 4);
    const unsigned myq0 = (lane & 3) * 2;

    for (int tile = blockIdx.x; tile < ntiles; tile += gridDim.x) {
        const long base = (long)tile * TM + w * 32;

        // ---- load + norm + convert (coalesced: warp-load = one 512B row) ----
        #pragma unroll 4
        for (int i = 0; i < 32; i++) {
            long g = base + i;
            float4 v = make_float4(0.f, 0.f, 0.f, 0.f);
            if (g < nrows) v = ((const float4*)corpus)[g * (DIM / 4) + lane];
            float n2 = warp_sum(fmaf(v.x, v.x, fmaf(v.y, v.y, fmaf(v.z, v.z, v.w * v.w))));
            if (lane == 0) sInv[w][i] = 1.0f / fmaxf(sqrtf(n2), 1e-12f);
            *(uint2*)((char*)&sA[w][i][0] + lane * 8) =
                make_uint2(pack_bf16x2(v.x, v.y), pack_bf16x2(v.z, v.w));
        }
        __syncwarp();

        // ---- per-tile effective thresholds (8 queries per thread) ----
        float eff[8];
        #pragma unroll
        for (int nt = 0; nt < 4; nt++)
            #pragma unroll
            for (int j = 0; j < 2; j++) {
                int qq = nt * 8 + myq0 + j;
                float gt = decf(__ldcg(&g_thresh_enc[qq])) - MARGIN;
                eff[nt * 2 + j] = fmaxf(sKmin[w][qq], gt);
            }

        // ---- 2 m-tiles of 16 rows ----
        #pragma unroll
        for (int mt = 0; mt < 2; mt++) {
            float d[16];
            #pragma unroll
            for (int i = 0; i < 16; i++) d[i] = 0.0f;

            #pragma unroll
            for (int kk = 0; kk < 8; kk++) {
                uint32_t a0, a1, a2, a3;
                ldm_x4(a0, a1, a2, a3, a_addr0 + mt * 4352 + kk * 32);
                #pragma unroll
                for (int nt = 0; nt < 4; nt++)
                    mma_bf16(&d[nt * 4], a0, a1, a2, a3, b[nt][kk][0], b[nt][kk][1]);
            }

            // ---- epilogue: scale by inv-norm, threshold, rare insert ----
            const int r0 = mt * 16 + (lane >> 2);
            const float i0 = sInv[w][r0], i1 = sInv[w][r0 + 8];
            const bool v0 = (base + r0) < nrows, v1 = (base + r0 + 8) < nrows;

            bool mine = false;
            #pragma unroll
            for (int nt = 0; nt < 4; nt++)
                #pragma unroll
                for (int j = 0; j < 4; j++) {
                    float sv = d[nt * 4 + j] * ((j < 2) ? i0 : i1);
                    bool va = (j < 2) ? v0 : v1;
                    mine |= va && (sv > eff[nt * 2 + (j & 1)]);
                }

            if (__ballot_sync(0xffffffffu, mine)) {
                #pragma unroll
                for (int nt = 0; nt < 4; nt++)
                    #pragma unroll
                    for (int j = 0; j < 4; j++) {
                        float sv = d[nt * 4 + j] * ((j < 2) ? i0 : i1);
                        bool va = (j < 2) ? v0 : v1;
                        unsigned m = __ballot_sync(0xffffffffu,
                                                   va && (sv > eff[nt * 2 + (j & 1)]));
                        if (!m) continue;
                        int rg = (int)(base + r0 + ((j < 2) ? 0 : 8));
                        while (m) {
                            int src = __ffs(m) - 1;
                            m &= m - 1;
                            float ssv = __shfl_sync(0xffffffffu, sv, src);
                            int srg = __shfl_sync(0xffffffffu, rg, src);
                            if (lane == 0) {
                                int qq = nt * 8 + ((src & 3) << 1) + (j & 1);
                                float* S = sTopS[w][qq];
                                int*   I = sTopI[w][qq];
                                float mn = S[0]; int mp = 0;
                                #pragma unroll
                                for (int t = 1; t < KTOP; t++)
                                    if (S[t] < mn) { mn = S[t]; mp = t; }
                                if (ssv > mn) {
                                    S[mp] = ssv; I[mp] = srg;
                                    mn = S[0];
                                    #pragma unroll
                                    for (int t = 1; t < KTOP; t++) mn = fminf(mn, S[t]);
                                    sKmin[w][qq] = mn;
                                    atomicMax(&g_thresh_enc[qq], encf(mn));
                                }
                            }
                        }
                        __syncwarp();
                    }
                // tighten cached thresholds after inserts
                #pragma unroll
                for (int nt = 0; nt < 4; nt++)
                    #pragma unroll
                    for (int j = 0; j < 2; j++)
                        eff[nt * 2 + j] = fmaxf(eff[nt * 2 + j], sKmin[w][nt * 8 + myq0 + j]);
            }
        }
    }

    // ---- writeback per-warp candidate lists ----
    __syncthreads();
    if (lane < KTOP) {
        int list = blockIdx.x * 4 + w;
        for (int c = 0; c < NQ; c++) {
            g_candS[(list * NQ + c) * KTOP + lane] = sTopS[w][c][lane];
            g_candI[(list * NQ + c) * KTOP + lane] = sTopI[w][c][lane];
        }
    }
}

// ============================================================
// Kernel 3: prune -> exact fp32 rescore (8 warps) -> exact top-10
// jax semantics: sorted desc, ties -> lower index first
// ============================================================
__global__ void merge_rescore(const float* __restrict__ corpus, float* __restrict__ out) {
    const int q = blockIdx.x;
    const float th = decf(g_thresh_enc[q]) - MARGIN;
    const int qb = q * POOLCAP;

    for (int j = threadIdx.x; j < NLISTS * KTOP; j += blockDim.x) {
        int l = j / KTOP, t = j - l * KTOP;
        float s = g_candS[(l * NQ + q) * KTOP + t];
        if (s >= th) {
            int pos = atomicAdd(&g_poolcnt[q], 1);
            g_poolS[qb + pos] = s;
            g_poolI[qb + pos] = g_candI[(l * NQ + q) * KTOP + t];
        }
    }
    __syncthreads();

    const int warp = threadIdx.x >> 5, lane = threadIdx.x & 31;
    int cnt = g_poolcnt[q];
    if (cnt > POOLCAP) cnt = POOLCAP;

    // distributed exact fp32 rescore
    float4 q4 = ((const float4*)g_qnf)[q * (DIM / 4) + lane];
    for (int i = warp; i < cnt; i += 8) {
        int idx = g_poolI[qb + i];
        float4 c4 = ((const float4*)corpus)[(long)idx * (DIM / 4) + lane];
        float d  = fmaf(c4.x, q4.x, fmaf(c4.y, q4.y, fmaf(c4.z, q4.z, c4.w * q4.w)));
        float n2 = fmaf(c4.x, c4.x, fmaf(c4.y, c4.y, fmaf(c4.z, c4.z, c4.w * c4.w)));
        #pragma unroll
        for (int o = 16; o; o >>= 1) {
            d  += __shfl_xor_sync(0xffffffffu, d, o);
            n2 += __shfl_xor_sync(0xffffffffu, n2, o);
        }
        if (lane == 0)
            g_poolS[qb + i] = d * (1.0f / fmaxf(sqrtf(n2), 1e-12f));
    }
    __syncthreads();

    if (warp != 0) return;
    for (int r = 0; r < KTOP; r++) {
        float bs = -FLT_MAX; int bi = 0x7fffffff; int bp = -1;
        for (int i = lane; i < cnt; i += 32) {
            float s = g_poolS[qb + i];
            int   x = g_poolI[qb + i];
            if (s > bs || (s == bs && x < bi)) { bs = s; bi = x; bp = i; }
        }
        #pragma unroll
        for (int o = 16; o; o >>= 1) {
            float os = __shfl_xor_sync(0xffffffffu, bs, o);
            int   oi = __shfl_xor_sync(0xffffffffu, bi, o);
            int   op = __shfl_xor_sync(0xffffffffu, bp, o);
            if (os > bs || (os == bs && oi < bi)) { bs = os; bi = oi; bp = op; }
        }
        if (lane == 0) {
            out[q * KTOP + r] = bs;
            out[NQ * KTOP + q * KTOP + r] = (float)bi;
            if (bp >= 0) { g_poolS[qb + bp] = -FLT_MAX; g_poolI[qb + bp] = 0x7fffffff; }
        }
        __threadfence_block();
        __syncwarp();
    }
}

// ============================================================
extern "C" void kernel_launch(void* const* d_in, const int* in_sizes, int n_in,
                              void* d_out, int out_size) {
    const float* queries = (const float*)d_in[0];
    const float* corpus  = (const float*)d_in[1];
    int nrows = in_sizes[1] / DIM;
    int ntiles = (nrows + TM - 1) / TM;

    prep_kernel<<<1, NQ * 32>>>(queries, corpus, nrows);
    score_mma<<<NBLK, TPB>>>(corpus, nrows, ntiles);
    merge_rescore<<<NQ, 256>>>(corpus, (float*)d_out);
}